// round 5
// baseline (speedup 1.0000x reference)
#include <cuda_runtime.h>
#include <cstdint>

// ---------------- problem constants ----------------
#define Bsz   16384
#define Sdim  256
#define Edim  128
#define Hdim  128
#define Ntask 34
#define TEMP_INV 10.0f

#define M_TILE  128
#define THREADS 256
#define NCTA    (Bsz / M_TILE)

// buffers: [128 rows][36 floats] (stride 144B -> conflict-free ldmatrix)
#define BUF_FLOATS (128 * 36)          // 4608
#define BUF_BYTES  (BUF_FLOATS * 4)    // 18432
#define LDSTRIDE   144                 // bytes per row

#define SLOTS      (16 * Ntask)        // 544

#define SMEM_FLOATS (8 * BUF_FLOATS + 2 * M_TILE * Ntask + 2 * M_TILE + 2 * M_TILE + M_TILE + M_TILE)
#define SMEM_BYTES  (SMEM_FLOATS * 4)  // 185,344

// ---------------- device scratch ----------------
__device__ float g_state[Bsz * Sdim];          // tf32-rounded state [b][s]
__device__ float g_W1T[Ntask * Hdim * Sdim];   // [n][h][k] K-major tf32
__device__ float g_W2T[Ntask * Hdim * Hdim];
__device__ float g_W3T[Ntask * Edim * Hdim];
__device__ float g_langn[Ntask * Edim];        // normalized lang_emb

// ---------------- helpers ----------------
__device__ __forceinline__ uint32_t smem_u32(const void* p) {
    uint32_t a;
    asm("{ .reg .u64 t; cvta.to.shared.u64 t, %1; cvt.u32.u64 %0, t; }" : "=r"(a) : "l"(p));
    return a;
}
__device__ __forceinline__ void cp16(uint32_t dst_s, const float* src) {
    asm volatile("cp.async.cg.shared.global [%0], [%1], 16;\n" :: "r"(dst_s), "l"(src));
}
#define CP_COMMIT()  asm volatile("cp.async.commit_group;\n" ::: "memory")
#define CP_WAIT2()   asm volatile("cp.async.wait_group 2;\n" ::: "memory")

__device__ __forceinline__ void ldsm4(uint32_t* r, uint32_t addr) {
    asm volatile("ldmatrix.sync.aligned.m8n8.x4.shared.b16 {%0,%1,%2,%3}, [%4];"
                 : "=r"(r[0]), "=r"(r[1]), "=r"(r[2]), "=r"(r[3]) : "r"(addr));
}
__device__ __forceinline__ void mma8(float& c0, float& c1, float& c2, float& c3,
                                     uint32_t a0, uint32_t a1, uint32_t a2, uint32_t a3,
                                     uint32_t b0, uint32_t b1) {
    asm volatile("mma.sync.aligned.m16n8k8.row.col.f32.tf32.tf32.f32 "
                 "{%0,%1,%2,%3},{%4,%5,%6,%7},{%8,%9},{%0,%1,%2,%3};\n"
                 : "+f"(c0), "+f"(c1), "+f"(c2), "+f"(c3)
                 : "r"(a0), "r"(a1), "r"(a2), "r"(a3), "r"(b0), "r"(b1));
}
__device__ __forceinline__ float quad_sum(float v) {
    v += __shfl_xor_sync(0xffffffffu, v, 1);
    v += __shfl_xor_sync(0xffffffffu, v, 2);
    return v;
}
__device__ __forceinline__ float to_tf32(float x) {
    uint32_t u;
    asm("cvt.rna.tf32.f32 %0, %1;" : "=r"(u) : "f"(x));
    return __uint_as_float(u);
}

// ---------------- prep kernels ----------------
__global__ void cvt_tf32_kernel(const float* __restrict__ src, float* __restrict__ dst, int n) {
    int i = blockIdx.x * blockDim.x + threadIdx.x;
    if (i < n) dst[i] = to_tf32(src[i]);
}

// transpose weights [K,H] -> [H,K] (tf32) + normalize lang
__global__ void prep_kernel(const float* __restrict__ W1, const float* __restrict__ W2,
                            const float* __restrict__ W3, const float* __restrict__ lang) {
    __shared__ float tile[32][33];
    int b = blockIdx.x, t = threadIdx.x;
    int tx = t & 31, ty = t >> 5;  // 32 x 8

    if (b >= 2176) {
        int nn = b - 2176;
        float v = 0.f, s = 0.f;
        if (t < 128) {
            v = lang[nn * Edim + t];
            s = v * v;
#pragma unroll
            for (int o = 16; o; o >>= 1) s += __shfl_xor_sync(0xffffffffu, s, o);
            if ((t & 31) == 0) tile[0][t >> 5] = s;
        }
        __syncthreads();
        if (t < 128) {
            float tot = tile[0][0] + tile[0][1] + tile[0][2] + tile[0][3];
            float nrm = fmaxf(sqrtf(tot), 1e-8f);
            g_langn[nn * Edim + t] = v / nrm;
        }
        return;
    }

    const float* src; float* dst; int K, H, n, tk, th;
    if (b < 1088)      { n = b >> 5; int tl = b & 31; K = Sdim; H = Hdim; tk = tl >> 2; th = tl & 3;
                         src = W1 + (size_t)n * K * H; dst = g_W1T + (size_t)n * H * K; }
    else if (b < 1632) { int bb = b - 1088; n = bb >> 4; int tl = bb & 15; K = Hdim; H = Hdim; tk = tl >> 2; th = tl & 3;
                         src = W2 + (size_t)n * K * H; dst = g_W2T + (size_t)n * H * K; }
    else               { int bb = b - 1632; n = bb >> 4; int tl = bb & 15; K = Hdim; H = Edim; tk = tl >> 2; th = tl & 3;
                         src = W3 + (size_t)n * K * H; dst = g_W3T + (size_t)n * H * K; }
    int k0 = tk * 32, h0 = th * 32;
#pragma unroll
    for (int i = 0; i < 4; ++i)
        tile[ty + i * 8][tx] = to_tf32(src[(size_t)(k0 + ty + i * 8) * H + h0 + tx]);
    __syncthreads();
#pragma unroll
    for (int i = 0; i < 4; ++i)
        dst[(size_t)(h0 + ty + i * 8) * K + k0 + tx] = tile[tx][ty + i * 8];
}

// ---------------- pipeline issue: one slot = B chunk (+ A chunk if slot<8) ----------------
__device__ __forceinline__ void issue_slot(int g, int bM, uint32_t aR, uint32_t bR, int tid) {
    if (g < SLOTS) {
        int n = g >> 4, s = g & 15;
        const float* bsrc; int ldk;
        if (s < 8)       { bsrc = g_W1T + (size_t)n * (Hdim * Sdim) + s * 32;        ldk = Sdim; }
        else if (s < 12) { bsrc = g_W2T + (size_t)n * (Hdim * Hdim) + (s - 8) * 32;  ldk = Hdim; }
        else             { bsrc = g_W3T + (size_t)n * (Edim * Hdim) + (s - 12) * 32; ldk = Hdim; }
        uint32_t bdst = bR + (uint32_t)(g & 3) * BUF_BYTES;
#pragma unroll
        for (int it = 0; it < 4; ++it) {
            int c = tid + it * THREADS;         // 0..1023
            int row = c >> 3, seg = c & 7;
            cp16(bdst + row * LDSTRIDE + seg * 16, bsrc + (size_t)row * ldk + seg * 4);
        }
        if (s < 8) {
            const float* asrc = g_state + (size_t)bM * Sdim + s * 32;
            uint32_t adst = aR + (uint32_t)(s & 3) * BUF_BYTES;
#pragma unroll
            for (int it = 0; it < 4; ++it) {
                int c = tid + it * THREADS;
                int row = c >> 3, seg = c & 7;
                cp16(adst + row * LDSTRIDE + seg * 16, asrc + (size_t)row * Sdim + seg * 4);
            }
        }
    }
    CP_COMMIT();   // empty groups at tail keep wait_group counting uniform
}

// ---------------- k32 slab: C[128x128] += A[128x32] x B[128n x 32k]^T ----------------
__device__ __forceinline__ void compute_slab(uint32_t aAddr, uint32_t bAddr,
                                             float (&acc)[2][8][4]) {
#pragma unroll
    for (int ks = 0; ks < 4; ++ks) {
        uint32_t a[2][4];
        ldsm4(a[0], aAddr + ks * 32);
        ldsm4(a[1], aAddr + 16 * LDSTRIDE + ks * 32);
        uint32_t b[4][4];
#pragma unroll
        for (int p = 0; p < 4; ++p)
            ldsm4(b[p], bAddr + p * (16 * LDSTRIDE) + ks * 32);
#pragma unroll
        for (int j = 0; j < 8; ++j) {
            uint32_t b0 = b[j >> 1][(j & 1) * 2];
            uint32_t b1 = b[j >> 1][(j & 1) * 2 + 1];
            mma8(acc[0][j][0], acc[0][j][1], acc[0][j][2], acc[0][j][3],
                 a[0][0], a[0][1], a[0][2], a[0][3], b0, b1);
            mma8(acc[1][j][0], acc[1][j][1], acc[1][j][2], acc[1][j][3],
                 a[1][0], a[1][1], a[1][2], a[1][3], b0, b1);
        }
    }
}

// ---------------- fused main kernel ----------------
__global__ __launch_bounds__(THREADS, 1)
void fused_kernel(const float* __restrict__ state_raw,
                  const int* __restrict__ task_id,
                  const float* __restrict__ prior,
                  const float* __restrict__ b1g,
                  const float* __restrict__ b2g,
                  const float* __restrict__ b3g,
                  float* __restrict__ out) {
    extern __shared__ __align__(16) float sm[];
    const uint32_t aR = smem_u32(sm);                       // A ring: 4 bufs (also holds h)
    const uint32_t bR = aR + 4 * BUF_BYTES;                 // B ring: 4 bufs
    float* p_s   = sm + 8 * BUF_FLOATS;                     // [128][34] softmax(prior)
    float* cos_s = p_s + M_TILE * Ntask;                    // [128][34]
    float* rpart = cos_s + M_TILE * Ntask;                  // 2*128
    float* cpart = rpart + 2 * M_TILE;                      // 2*128
    float* invn  = cpart + 2 * M_TILE;                      // 128
    int*   tids  = (int*)(invn + M_TILE);                   // 128

    const int tid  = threadIdx.x;
    const int bM   = blockIdx.x * M_TILE;
    const int lane = tid & 31;
    const int warp = tid >> 5;
    const int wm = warp >> 1, wn = warp & 1;
    const int grp = lane >> 2, tig = lane & 3;
    const int quad = lane >> 3, r8 = lane & 7;

    // per-lane ldmatrix offsets (within a buffer)
    const uint32_t aLane = (uint32_t)((wm * 32 + (quad & 1) * 8 + r8) * LDSTRIDE + (quad >> 1) * 16);
    const uint32_t bLane = (uint32_t)((wn * 64 + (quad >> 1) * 8 + r8) * LDSTRIDE + (quad & 1) * 16);

    float* out_rep  = out;
    float* out_logp = out + (size_t)Bsz * (Sdim + Edim);
    float* out_tgt  = out_logp + (size_t)Bsz * Ntask;
    float* out_lat  = out_tgt + (size_t)Bsz * Edim;

    // ---- prologue: task ids + softmax(prior) ----
    if (tid < M_TILE) {
        tids[tid] = task_id[bM + tid];
        const float* pr = prior + (size_t)(bM + tid) * Ntask;
        float mx = -1e30f;
        for (int i = 0; i < Ntask; ++i) mx = fmaxf(mx, pr[i]);
        float s = 0.f;
        for (int i = 0; i < Ntask; ++i) s += expf(pr[i] - mx);
        float inv = 1.0f / s;
        for (int i = 0; i < Ntask; ++i) p_s[tid * Ntask + i] = expf(pr[i] - mx) * inv;
    }

    float lat[2][8][4];
    float acc[2][8][4];
#pragma unroll
    for (int t = 0; t < 2; ++t)
#pragma unroll
        for (int j = 0; j < 8; ++j)
#pragma unroll
            for (int i = 0; i < 4; ++i) { lat[t][j][i] = 0.f; acc[t][j][i] = 0.f; }

    __syncthreads();

    // prefetch slots 0,1,2
    issue_slot(0, bM, aR, bR, tid);
    issue_slot(1, bM, aR, bR, tid);
    issue_slot(2, bM, aR, bR, tid);

#pragma unroll 1
    for (int g = 0; g < SLOTS; ++g) {
        const int n = g >> 4, s = g & 15;

        CP_WAIT2();          // slot g's group complete
        __syncthreads();     // visible to all threads; all readers of buf (g-1)&3 done
        issue_slot(g + 3, bM, aR, bR, tid);

        // A operand buffer: GEMM1 streams state; GEMM2/3 read resident h/h2
        uint32_t aBase;
        if (s < 8)       aBase = aR + (uint32_t)(s & 3) * BUF_BYTES;
        else if (s < 12) aBase = aR + (uint32_t)(s - 8) * BUF_BYTES;
        else             aBase = aR + (uint32_t)(s - 12) * BUF_BYTES;

        compute_slab(aBase + aLane, bR + (uint32_t)(g & 3) * BUF_BYTES + bLane, acc);

        if (s == 7 || s == 11) {
            // layer boundary: h = tf32(relu(acc + bias)) -> A ring (warp-row-local)
            const float* bb = (s == 7 ? b1g + n * Hdim : b2g + n * Hdim);
#pragma unroll
            for (int t = 0; t < 2; ++t)
#pragma unroll
                for (int j = 0; j < 8; ++j)
#pragma unroll
                    for (int i = 0; i < 4; ++i) {
                        int row = wm * 32 + t * 16 + (i >> 1) * 8 + grp;
                        int col = wn * 64 + j * 8 + tig * 2 + (i & 1);
                        float v = fmaxf(acc[t][j][i] + __ldg(bb + col), 0.f);
                        uint32_t dst = aR + (uint32_t)(col >> 5) * BUF_BYTES
                                     + (uint32_t)(row * LDSTRIDE + (col & 31) * 4);
                        *(float*)__cvta_shared_to_generic(dst) = to_tf32(v);
                        acc[t][j][i] = 0.f;
                    }
        } else if (s == 15) {
            // ---------- per-task epilogue ----------
            const float* bb = b3g + n * Edim;
#pragma unroll
            for (int t = 0; t < 2; ++t)
#pragma unroll
                for (int j = 0; j < 8; ++j)
#pragma unroll
                    for (int i = 0; i < 4; ++i) {
                        int col = wn * 64 + j * 8 + tig * 2 + (i & 1);
                        acc[t][j][i] += __ldg(bb + col);
                    }
            float pr4[4] = {0.f, 0.f, 0.f, 0.f};
#pragma unroll
            for (int t = 0; t < 2; ++t)
#pragma unroll
                for (int j = 0; j < 8; ++j)
#pragma unroll
                    for (int i = 0; i < 4; ++i)
                        pr4[t * 2 + (i >> 1)] += acc[t][j][i] * acc[t][j][i];
#pragma unroll
            for (int k = 0; k < 4; ++k) pr4[k] = quad_sum(pr4[k]);
            if (tig == 0) {
#pragma unroll
                for (int k = 0; k < 4; ++k) {
                    int row = wm * 32 + (k >> 1) * 16 + (k & 1) * 8 + grp;
                    rpart[wn * M_TILE + row] = pr4[k];
                }
            }
            __syncthreads();
            if (tid < M_TILE) invn[tid] = rsqrtf(rpart[tid] + rpart[M_TILE + tid]);
            __syncthreads();

            float cp4[4] = {0.f, 0.f, 0.f, 0.f};
#pragma unroll
            for (int t = 0; t < 2; ++t)
#pragma unroll
                for (int i2 = 0; i2 < 2; ++i2) {
                    int row = wm * 32 + t * 16 + i2 * 8 + grp;
                    float iv = invn[row];
                    int tt = tids[row];
                    float pw = p_s[row * Ntask + n];
                    const float* lrow = g_langn + tt * Edim;
                    bool hit = (tt == n);
                    float* tgt = out_tgt + (size_t)(bM + row) * Edim;
#pragma unroll
                    for (int j = 0; j < 8; ++j)
#pragma unroll
                        for (int ih = 0; ih < 2; ++ih) {
                            int i = i2 * 2 + ih;
                            int col = wn * 64 + j * 8 + tig * 2 + ih;
                            float qn = acc[t][j][i] * iv;
                            cp4[t * 2 + i2] += qn * __ldg(lrow + col);
                            lat[t][j][i] += qn * pw;
                            if (hit) tgt[col] = qn;
                            acc[t][j][i] = 0.f;   // reset for next task
                        }
                }
#pragma unroll
            for (int k = 0; k < 4; ++k) cp4[k] = quad_sum(cp4[k]);
            if (tig == 0) {
#pragma unroll
                for (int k = 0; k < 4; ++k) {
                    int row = wm * 32 + (k >> 1) * 16 + (k & 1) * 8 + grp;
                    cpart[wn * M_TILE + row] = cp4[k];
                }
            }
            __syncthreads();
            if (tid < M_TILE) cos_s[tid * Ntask + n] = cpart[tid] + cpart[M_TILE + tid];
        }
    }

    __syncthreads();

    // ---------- final epilogue ----------
    if (tid < M_TILE) {
        int rowg = bM + tid;
        const float* cr = cos_s + tid * Ntask;
        float mx = -1e30f;
        for (int nn = 0; nn < Ntask; ++nn) mx = fmaxf(mx, cr[nn] * TEMP_INV);
        float s = 0.f;
        for (int nn = 0; nn < Ntask; ++nn) s += expf(cr[nn] * TEMP_INV - mx);
        float lse = logf(s);
        float* op = out_logp + (size_t)rowg * Ntask;
        for (int nn = 0; nn < Ntask; ++nn) op[nn] = cr[nn] * TEMP_INV - mx - lse;
    }
    // latent_vec + rep_vec latent half
#pragma unroll
    for (int t = 0; t < 2; ++t)
#pragma unroll
        for (int j = 0; j < 8; ++j)
#pragma unroll
            for (int i = 0; i < 4; ++i) {
                int row = wm * 32 + t * 16 + (i >> 1) * 8 + grp;
                int col = wn * 64 + j * 8 + tig * 2 + (i & 1);
                float v = lat[t][j][i];
                size_t rg = (size_t)(bM + row);
                out_lat[rg * Edim + col] = v;
                out_rep[rg * (Sdim + Edim) + Sdim + col] = v;
            }
    // rep_vec state half (original fp32 state)
    for (int idx = tid; idx < M_TILE * Sdim; idx += THREADS) {
        int r = idx >> 8, c = idx & 255;
        out_rep[(size_t)(bM + r) * (Sdim + Edim) + c] =
            state_raw[(size_t)(bM + r) * Sdim + c];
    }
}

// ---------------- launch ----------------
extern "C" void kernel_launch(void* const* d_in, const int* in_sizes, int n_in,
                              void* d_out, int out_size) {
    const float* state = (const float*)d_in[0];
    const int*   task  = (const int*)d_in[1];
    const float* prior = (const float*)d_in[2];
    const float* W1    = (const float*)d_in[3];
    const float* b1    = (const float*)d_in[4];
    const float* W2    = (const float*)d_in[5];
    const float* b2    = (const float*)d_in[6];
    const float* W3    = (const float*)d_in[7];
    const float* b3    = (const float*)d_in[8];
    const float* lang  = (const float*)d_in[9];
    float* out = (float*)d_out;

    float* gs;
    cudaGetSymbolAddress((void**)&gs, g_state);
    int n1 = Bsz * Sdim;
    cvt_tf32_kernel<<<(n1 + 255) / 256, 256>>>(state, gs, n1);
    prep_kernel<<<2176 + Ntask, 256>>>(W1, W2, W3, lang);

    cudaFuncSetAttribute(fused_kernel, cudaFuncAttributeMaxDynamicSharedMemorySize, SMEM_BYTES);
    fused_kernel<<<NCTA, THREADS, SMEM_BYTES>>>(state, task, prior, b1, b2, b3, out);
}